// round 10
// baseline (speedup 1.0000x reference)
#include <cuda_runtime.h>
#include <cuda_fp16.h>
#include <cstdint>
#include <math.h>

// ---------------------------------------------------------------------------
// Problem constants
// ---------------------------------------------------------------------------
#define N_CLASS 10000
#define EMB     512
#define HID     1024
#define BATCH   64
#define SEQ     128
#define G4      (4*HID)          // 4096 gate columns (interleaved J = 4u+g)
#define ROWS    (SEQ*BATCH)      // 8192

// ---------------------------------------------------------------------------
// mma.sync / ldmatrix / cp.async helpers (arch-portable sm_80+ path)
// ---------------------------------------------------------------------------
__device__ __forceinline__ uint32_t smem_u32(const void* p) {
    uint32_t a;
    asm("{ .reg .u64 t; cvta.to.shared.u64 t, %1; cvt.u32.u64 %0, t; }"
        : "=r"(a) : "l"(p));
    return a;
}

__device__ __forceinline__ void ldmatrix_x4(uint32_t* r, uint32_t addr) {
    asm volatile("ldmatrix.sync.aligned.m8n8.x4.shared.b16 {%0,%1,%2,%3}, [%4];"
                 : "=r"(r[0]), "=r"(r[1]), "=r"(r[2]), "=r"(r[3]) : "r"(addr));
}

// D(f32) += A(f16) * B(f16), m16n8k16, A row-major, B col-major
__device__ __forceinline__ void mma16816(float* d, const uint32_t* a,
                                         const uint32_t* b) {
    asm volatile(
        "mma.sync.aligned.m16n8k16.row.col.f32.f16.f16.f32 "
        "{%0,%1,%2,%3}, {%4,%5,%6,%7}, {%8,%9}, {%0,%1,%2,%3};"
        : "+f"(d[0]), "+f"(d[1]), "+f"(d[2]), "+f"(d[3])
        : "r"(a[0]), "r"(a[1]), "r"(a[2]), "r"(a[3]),
          "r"(b[0]), "r"(b[1]));
}

__device__ __forceinline__ void cpa16(uint32_t s, const void* g) {
    asm volatile("cp.async.cg.shared.global [%0], [%1], 16;" :: "r"(s), "l"(g));
}
__device__ __forceinline__ void cpa_commit() {
    asm volatile("cp.async.commit_group;");
}
template<int N> __device__ __forceinline__ void cpa_wait() {
    asm volatile("cp.async.wait_group %0;" :: "n"(N));
}

__device__ __forceinline__ void st_release(unsigned* p, unsigned v) {
    asm volatile("st.release.gpu.u32 [%0], %1;" :: "l"(p), "r"(v) : "memory");
}
__device__ __forceinline__ unsigned ld_acquire(const unsigned* p) {
    unsigned v;
    asm volatile("ld.acquire.gpu.u32 %0, [%1];" : "=r"(v) : "l"(p) : "memory");
    return v;
}

// Hardware-approx activations (sm_75+)
__device__ __forceinline__ float fast_tanh(float x) {
    float r;
    asm("tanh.approx.f32 %0, %1;" : "=f"(r) : "f"(x));
    return r;
}
__device__ __forceinline__ float fast_sig(float x) {
    float e;
    asm("ex2.approx.f32 %0, %1;" : "=f"(e) : "f"(-1.4426950408889634f * x));
    float r;
    asm("rcp.approx.f32 %0, %1;" : "=f"(r) : "f"(1.0f + e));
    return r;
}

// ---------------------------------------------------------------------------
// Device scratch (static; no cudaMalloc allowed)
// ---------------------------------------------------------------------------
__device__ __half g_E  [ROWS*EMB];      // embeddings fp16, row = t*64+b
__device__ __half g_H  [ROWS*HID];      // layer0 h: [t][m][u] fp16
__device__ __half g_H1 [ROWS*HID];      // layer1 h: [t][m][u] fp16
__device__ __half g_B0 [G4*EMB];        // input weights L0 [J=4u+g][k]
__device__ __half g_B1 [G4*HID];        // input weights L1
__device__ __half g_R0 [G4*HID];        // recurrent weights L0 [J][k]
__device__ __half g_R1 [G4*HID];        // recurrent weights L1
__device__ float g_XG0[ROWS*G4];
__device__ float g_XG1[ROWS*G4];
__device__ float g_b0 [G4];
__device__ float g_b1 [G4];
__device__ __half g_hz [BATCH*HID];     // zero h
__device__ float g_h1f [BATCH*HID];     // layer1 final h fp32
__device__ unsigned g_pflags[2*128*8];  // per-block step flags (x8 padded)

// ---------------------------------------------------------------------------
// Prep kernels
// ---------------------------------------------------------------------------
struct WcvtArgs {
    const float* src[16];
    __half* dst[16];
    int K[16];
    int g[16];
};

// W[K][1024](fp32, col u) -> dst[4u+g][K] fp16; one launch for all 16 mats.
__global__ void wcvt_all(WcvtArgs a)
{
    __shared__ float s[32][33];
    const int z = blockIdx.z;
    const int K = a.K[z];
    const int k0 = blockIdx.x * 32;
    if (k0 >= K) return;
    const float* W = a.src[z];
    __half* B = a.dst[z];
    const int g = a.g[z];
    const int u0 = blockIdx.y * 32;
    const int tx = threadIdx.x, ty = threadIdx.y;        // (32, 8)
#pragma unroll
    for (int j = 0; j < 4; j++)
        s[ty + j*8][tx] = W[(size_t)(k0 + ty + j*8) * HID + u0 + tx];
    __syncthreads();
#pragma unroll
    for (int j = 0; j < 4; j++) {
        int uu = ty + j*8;
        B[(size_t)(4*(u0 + uu) + g) * K + k0 + tx] = __float2half(s[tx][uu]);
    }
}

__global__ void pack_b4(const float* __restrict__ a, const float* __restrict__ b,
                        const float* __restrict__ c, const float* __restrict__ d,
                        float4* __restrict__ dst)
{
    int u = blockIdx.x * blockDim.x + threadIdx.x;
    if (u < HID) dst[u] = make_float4(a[u], b[u], c[u], d[u]);
}

__global__ void zero_init(__half* __restrict__ hz,
                          unsigned* __restrict__ pflags)
{
    int idx = blockIdx.x * blockDim.x + threadIdx.x;
    if (idx < BATCH * HID) hz[idx] = __float2half(0.f);
    if (idx < 2*128*8) pflags[idx] = 0;
}

__global__ void embed_f16(const int* __restrict__ X, const float* __restrict__ C,
                          __half* __restrict__ E)
{
    int idx = blockIdx.x * blockDim.x + threadIdx.x;
    if (idx < ROWS * EMB) {
        int row = idx >> 9, e = idx & 511;
        int t = row >> 6, b = row & 63;
        int tok = X[b * SEQ + t];
        E[idx] = __float2half(C[(size_t)tok * EMB + e]);
    }
}

// ---------------------------------------------------------------------------
// HMMA fp16 GEMM with 2-stage cp.async pipeline:
// C[M][4096] = A[M][K] @ B[4096][K]^T, 128x64 tile, 256 thr.
// ---------------------------------------------------------------------------
#define MM_STAGE 15360
#define MM_SMEM  (2*MM_STAGE)
__global__ __launch_bounds__(256)
void mm_mma(const __half* __restrict__ Ag, const __half* __restrict__ Bg,
            float* __restrict__ Cm, int K)
{
    extern __shared__ __align__(16) char smc[];
    const int tid = threadIdx.x, lane = tid & 31, w = tid >> 5;
    const int m0 = blockIdx.y * 128, n0 = blockIdx.x * 64;
    const int wm = (w & 3) * 32, wn = (w >> 2) * 32;
    const int g = lane >> 2, tig = lane & 3;
    const int sub = lane >> 3, lr = lane & 7;
    const uint32_t sbase = smem_u32(smc);

    float acc[2][4][4];
#pragma unroll
    for (int ti = 0; ti < 2; ti++)
#pragma unroll
        for (int j = 0; j < 4; j++)
#pragma unroll
            for (int q = 0; q < 4; q++) acc[ti][j][q] = 0.f;

    uint32_t aOff[2];
#pragma unroll
    for (int ti = 0; ti < 2; ti++)
        aOff[ti] = (wm + ti*16 + (sub & 1)*8 + lr)*80 + (sub >> 1)*16;

    const int ar = tid >> 2, as4 = tid & 3;

    auto issue = [&](int c) {
        uint32_t base = sbase + (c & 1) * MM_STAGE;
        size_t kb = (size_t)c * 32;
#pragma unroll
        for (int i = 0; i < 2; i++) {
            int r = ar + i * 64;
            cpa16(base + r*80 + as4*16, Ag + (size_t)(m0 + r) * K + kb + as4*8);
        }
        cpa16(base + 10240 + ar*80 + as4*16,
              Bg + (size_t)(n0 + ar) * K + kb + as4*8);
        cpa_commit();
    };

    issue(0);
    const int nchunk = K >> 5;
    for (int c = 0; c < nchunk; c++) {
        __syncthreads();
        if (c + 1 < nchunk) { issue(c + 1); cpa_wait<1>(); }
        else                { cpa_wait<0>(); }
        __syncthreads();

        const uint32_t st = sbase + (c & 1) * MM_STAGE;
        const uint32_t stRel = (c & 1) * MM_STAGE;
#pragma unroll
        for (int ks = 0; ks < 2; ks++) {
            uint32_t a[2][4];
#pragma unroll
            for (int ti = 0; ti < 2; ti++)
                ldmatrix_x4(a[ti], st + aOff[ti] + ks*32);
            uint32_t bh[4][2];
#pragma unroll
            for (int j = 0; j < 4; j++) {
                uint32_t off = stRel + 10240 + (wn + 8*j + g)*80 + ks*32 + tig*4;
                bh[j][0] = *(const uint32_t*)(smc + off);
                bh[j][1] = *(const uint32_t*)(smc + off + 16);
            }
#pragma unroll
            for (int ti = 0; ti < 2; ti++)
#pragma unroll
                for (int j = 0; j < 4; j++)
                    mma16816(acc[ti][j], a[ti], bh[j]);
        }
    }

#pragma unroll
    for (int ti = 0; ti < 2; ti++) {
        int row = m0 + wm + ti*16 + g;
#pragma unroll
        for (int j = 0; j < 4; j++) {
            int col = n0 + wn + 8*j + tig*2;
            *(float2*)&Cm[(size_t)row * G4 + col] =
                make_float2(acc[ti][j][0], acc[ti][j][1]);
            *(float2*)&Cm[(size_t)(row + 8) * G4 + col] =
                make_float2(acc[ti][j][2], acc[ti][j][3]);
        }
    }
}

// ---------------------------------------------------------------------------
// Persistent LSTM recurrence kernel (fp16, whole-h in smem).
// 128 blocks x 256 thr. Block owns 32 gate columns; weight slice (32x1024
// fp16 = 66KB, INTERLEAVED b0/b1 pair layout) + TWO h-halves in smem.
// Even/odd k-slice accumulator split: 4 independent MMA chains per warp
// (8 per SMSP) to cover HMMA dependency latency.
// Weight smem layout per row, per k16 group (32B): words interleaved so a
// thread's (b0,b1) fragment pair is one aligned LDS.64:
//   new word (ks*8 + 2t + h) = old word (ks*8 + h*4 + t),  t=0..3, h=0..1
// ---------------------------------------------------------------------------
#define PW 2064                       // weight smem row pitch (2048 + 16 pad)
#define PAH 1040                      // A-half row pitch (1024 + 16 pad)
#define W_BYTES (32*PW)               // 66048
#define A_HALF (64*PAH)               // 66560
#define A_OFF   W_BYTES
#define SM_PERSIST (A_OFF + 2*A_HALF) // 199168

__global__ __launch_bounds__(256, 1)
void lstm_persist(const __half* __restrict__ Wg,
                  const float* __restrict__ XG, const float* __restrict__ bias,
                  const __half* __restrict__ hz,
                  __half* __restrict__ Hout,        // [SEQ][64][1024]
                  float* __restrict__ hf,
                  unsigned* __restrict__ pflags)    // [128] x8-padded
{
    extern __shared__ __align__(16) char sm[];
    char* sW = sm;
    const uint32_t aAbs = smem_u32(sm) + A_OFF;

    const int tid = threadIdx.x, lane = tid & 31, w = tid >> 5;
    const int wr = w & 3, wc = w >> 2;
    const int g = lane >> 2, tig = lane & 3;
    const int sub = lane >> 3, lr = lane & 7;
    const int n0 = blockIdx.x * 32;

    // ---- load this block's weight slice into smem with pair-interleave ----
    // new word (ks*8 + 2t + h) <- global word (ks*8 + h*4 + t)
    for (int idx = tid; idx < 32*512; idx += 256) {
        int r = idx >> 9, wd = idx & 511;
        int ks = wd >> 3, t = (wd >> 1) & 3, h = wd & 1;
        const uint32_t* src = (const uint32_t*)(Wg + ((size_t)(n0 + r) << 10));
        *(uint32_t*)(sW + r*PW + wd*4) = src[ks*8 + h*4 + t];
    }
    __syncthreads();

    const uint32_t rowoff = (16*wr + (sub & 1)*8 + lr)*PAH + (sub >> 1)*16;
    const int brow0 = (wc*16 + g)*PW + tig*8;
    const int brow1 = (wc*16 + 8 + g)*PW + tig*8;
    const int m1 = 16*wr + g, m2 = m1 + 8;
    const int Jc0 = n0 + wc*16 + tig*2;
    const int Jc1 = Jc0 + 8;
    const float2 bb0 = *(const float2*)&bias[Jc0];
    const float2 bb1 = *(const float2*)&bias[Jc1];
    const bool co = (tig & 1);
    const int u0 = Jc0 >> 2, u1 = Jc1 >> 2;

    float cc00 = 0.f, cc01 = 0.f, cc10 = 0.f, cc11 = 0.f;

    for (int t = 0; t < SEQ; t++) {
        const __half* ph = t ? (Hout + (size_t)(t-1) * BATCH * HID) : hz;
        __half* dh = Hout + (size_t)t * BATCH * HID;

        // prefetch xg for this step (independent of the recurrence chain)
        const float* xb = XG + (((size_t)(t*64)) << 12);
        const float2 x1_0 = *(const float2*)(xb + (size_t)m1*G4 + Jc0);
        const float2 x2_0 = *(const float2*)(xb + (size_t)m2*G4 + Jc0);
        const float2 x1_1 = *(const float2*)(xb + (size_t)m1*G4 + Jc1);
        const float2 x2_1 = *(const float2*)(xb + (size_t)m2*G4 + Jc1);

        // issue one 64x512 half (64 KB) of h_prev into smem buffer `half`
        auto issue = [&](int half) {
            uint32_t dst = aAbs + half * A_HALF;
            const __half* src = ph + half * 512;
#pragma unroll
            for (int i = 0; i < 16; i++) {
                int lin = tid + i * 256;
                int r = lin >> 6, s = lin & 63;
                cpa16(dst + r*PAH + s*16, src + ((size_t)r << 10) + s*8);
            }
            cpa_commit();
        };

        issue(0);
        issue(1);

        // 4 independent accumulator chains per warp (even/odd k-slices)
        float acc0a[4] = {0.f, 0.f, 0.f, 0.f};
        float acc0b[4] = {0.f, 0.f, 0.f, 0.f};
        float acc1a[4] = {0.f, 0.f, 0.f, 0.f};
        float acc1b[4] = {0.f, 0.f, 0.f, 0.f};

#pragma unroll
        for (int half = 0; half < 2; half++) {
            if (half == 0) cpa_wait<1>(); else cpa_wait<0>();
            __syncthreads();
            const uint32_t ah = aAbs + half * A_HALF + rowoff;
            const int kbase = half * 1024;     // byte offset into weight row
#pragma unroll 8
            for (int ks = 0; ks < 32; ks += 2) {
                uint32_t aE[4], aO[4];
                ldmatrix_x4(aE, ah + ks*32);
                ldmatrix_x4(aO, ah + ks*32 + 32);
                const int ko = kbase + ks*32;
                uint2 w0e = *(const uint2*)(sW + brow0 + ko);
                uint2 w1e = *(const uint2*)(sW + brow1 + ko);
                uint2 w0o = *(const uint2*)(sW + brow0 + ko + 32);
                uint2 w1o = *(const uint2*)(sW + brow1 + ko + 32);
                mma16816(acc0a, aE, (const uint32_t*)&w0e);
                mma16816(acc1a, aE, (const uint32_t*)&w1e);
                mma16816(acc0b, aO, (const uint32_t*)&w0o);
                mma16816(acc1b, aO, (const uint32_t*)&w1o);
            }
        }

        float acc0[4], acc1[4];
#pragma unroll
        for (int q = 0; q < 4; q++) {
            acc0[q] = acc0a[q] + acc0b[q];
            acc1[q] = acc1a[q] + acc1b[q];
        }

        // ---- pointwise epilogue (hardware-approx activations) ----
        {
            float p0 = acc0[0] + x1_0.x + bb0.x;
            float p1 = acc0[1] + x1_0.y + bb0.y;
            float p2 = acc0[2] + x2_0.x + bb0.x;
            float p3 = acc0[3] + x2_0.y + bb0.y;
            float a0v = co ? fast_tanh(p0) : fast_sig(p0);
            float a1v = fast_sig(p1);
            float a2v = co ? fast_tanh(p2) : fast_sig(p2);
            float a3v = fast_sig(p3);
            float C1 = __shfl_xor_sync(0xFFFFFFFFu, a0v, 1);
            float O1 = __shfl_xor_sync(0xFFFFFFFFu, a1v, 1);
            float C2 = __shfl_xor_sync(0xFFFFFFFFu, a2v, 1);
            float O2 = __shfl_xor_sync(0xFFFFFFFFu, a3v, 1);
            if (!co) {
                cc00 = a0v * cc00 + a1v * C1;
                float hv = O1 * fast_tanh(cc00);
                dh[m1*HID + u0] = __float2half(hv);
                if (hf && t == SEQ-1) hf[m1*HID + u0] = hv;
                cc01 = a2v * cc01 + a3v * C2;
                hv = O2 * fast_tanh(cc01);
                dh[m2*HID + u0] = __float2half(hv);
                if (hf && t == SEQ-1) hf[m2*HID + u0] = hv;
            }
        }
        {
            float p0 = acc1[0] + x1_1.x + bb1.x;
            float p1 = acc1[1] + x1_1.y + bb1.y;
            float p2 = acc1[2] + x2_1.x + bb1.x;
            float p3 = acc1[3] + x2_1.y + bb1.y;
            float a0v = co ? fast_tanh(p0) : fast_sig(p0);
            float a1v = fast_sig(p1);
            float a2v = co ? fast_tanh(p2) : fast_sig(p2);
            float a3v = fast_sig(p3);
            float C1 = __shfl_xor_sync(0xFFFFFFFFu, a0v, 1);
            float O1 = __shfl_xor_sync(0xFFFFFFFFu, a1v, 1);
            float C2 = __shfl_xor_sync(0xFFFFFFFFu, a2v, 1);
            float O2 = __shfl_xor_sync(0xFFFFFFFFu, a3v, 1);
            if (!co) {
                cc10 = a0v * cc10 + a1v * C1;
                float hv = O1 * fast_tanh(cc10);
                dh[m1*HID + u1] = __float2half(hv);
                if (hf && t == SEQ-1) hf[m1*HID + u1] = hv;
                cc11 = a2v * cc11 + a3v * C2;
                hv = O2 * fast_tanh(cc11);
                dh[m2*HID + u1] = __float2half(hv);
                if (hf && t == SEQ-1) hf[m2*HID + u1] = hv;
            }
        }

        // ---- flat one-hop grid barrier (skip after last step) ----
        if (t != SEQ-1) {
            const unsigned sense = (unsigned)(t + 1);
            __syncthreads();              // all h stores in this block done
            if (tid == 0)
                st_release(pflags + blockIdx.x*8, sense);
            if (tid < 128) {
                const unsigned* f = pflags + tid*8;
                while (ld_acquire(f) < sense) {}
            }
            __syncthreads();
        }
    }
}

// ---------------------------------------------------------------------------
// Output projection: out[64][N] = A[64][K] @ B[K][N] + bias (fp32)
// ---------------------------------------------------------------------------
__global__ __launch_bounds__(256)
void sgemm_out(const float* __restrict__ A, const float* __restrict__ B,
               float* __restrict__ Cmat, int N, int K, const float* __restrict__ bias)
{
    __shared__ __align__(16) float As[16][68];
    __shared__ __align__(16) float Bs[16][68];

    const int tid = threadIdx.x;
    const int tx = tid & 15, ty = tid >> 4;
    const int n0 = blockIdx.x * 64;

    float acc[4][4];
#pragma unroll
    for (int r = 0; r < 4; r++)
#pragma unroll
        for (int c = 0; c < 4; c++) acc[r][c] = 0.f;

    const int am = tid >> 2;
    const int akg = tid & 3;
    const int bk = tid >> 4;
    const int bn4 = tid & 15;

    for (int k0 = 0; k0 < K; k0 += 16) {
        float4 av = *(const float4*)&A[(size_t)am * K + k0 + akg * 4];
        float4 bv;
        if (n0 + bn4 * 4 < N)
            bv = *(const float4*)&B[(size_t)(k0 + bk) * N + n0 + bn4 * 4];
        else
            bv = make_float4(0.f, 0.f, 0.f, 0.f);
        As[akg*4 + 0][am] = av.x;
        As[akg*4 + 1][am] = av.y;
        As[akg*4 + 2][am] = av.z;
        As[akg*4 + 3][am] = av.w;
        *(float4*)&Bs[bk][bn4 * 4] = bv;
        __syncthreads();
#pragma unroll
        for (int kk = 0; kk < 16; kk++) {
            float4 a4 = *(const float4*)&As[kk][ty * 4];
            float4 b4 = *(const float4*)&Bs[kk][tx * 4];
            acc[0][0] = fmaf(a4.x, b4.x, acc[0][0]);
            acc[0][1] = fmaf(a4.x, b4.y, acc[0][1]);
            acc[0][2] = fmaf(a4.x, b4.z, acc[0][2]);
            acc[0][3] = fmaf(a4.x, b4.w, acc[0][3]);
            acc[1][0] = fmaf(a4.y, b4.x, acc[1][0]);
            acc[1][1] = fmaf(a4.y, b4.y, acc[1][1]);
            acc[1][2] = fmaf(a4.y, b4.z, acc[1][2]);
            acc[1][3] = fmaf(a4.y, b4.w, acc[1][3]);
            acc[2][0] = fmaf(a4.z, b4.x, acc[2][0]);
            acc[2][1] = fmaf(a4.z, b4.y, acc[2][1]);
            acc[2][2] = fmaf(a4.z, b4.z, acc[2][2]);
            acc[2][3] = fmaf(a4.z, b4.w, acc[2][3]);
            acc[3][0] = fmaf(a4.w, b4.x, acc[3][0]);
            acc[3][1] = fmaf(a4.w, b4.y, acc[3][1]);
            acc[3][2] = fmaf(a4.w, b4.z, acc[3][2]);
            acc[3][3] = fmaf(a4.w, b4.w, acc[3][3]);
        }
        __syncthreads();
    }

#pragma unroll
    for (int r = 0; r < 4; r++) {
        int m = ty * 4 + r;
#pragma unroll
        for (int c = 0; c < 4; c++) {
            int n = n0 + tx * 4 + c;
            if (n < N) Cmat[(size_t)m * N + n] = acc[r][c] + bias[n];
        }
    }
}

// ---------------------------------------------------------------------------
// Host launcher (graph-capturable: kernel launches only)
// ---------------------------------------------------------------------------
extern "C" void kernel_launch(void* const* d_in, const int* in_sizes, int n_in,
                              void* d_out, int out_size)
{
    const int*   X     = (const int*)  d_in[0];
    const float* Cemb  = (const float*)d_in[1];
    const float* W_fx  = (const float*)d_in[2];
    const float* W_fh  = (const float*)d_in[3];
    const float* W_ix  = (const float*)d_in[4];
    const float* W_ih  = (const float*)d_in[5];
    const float* W_Cx  = (const float*)d_in[6];
    const float* W_Ch  = (const float*)d_in[7];
    const float* W_ox  = (const float*)d_in[8];
    const float* W_oh  = (const float*)d_in[9];
    const float* W_fx1 = (const float*)d_in[10];
    const float* W_fh1 = (const float*)d_in[11];
    const float* W_ix1 = (const float*)d_in[12];
    const float* W_ih1 = (const float*)d_in[13];   // unused (reference bug kept)
    const float* W_Cx1 = (const float*)d_in[14];
    const float* W_Ch1 = (const float*)d_in[15];
    const float* W_ox1 = (const float*)d_in[16];
    const float* W_oh1 = (const float*)d_in[17];
    const float* W_out = (const float*)d_in[18];
    const float* b_f   = (const float*)d_in[19];
    const float* b_i   = (const float*)d_in[20];
    const float* b_C   = (const float*)d_in[21];
    const float* b_o   = (const float*)d_in[22];
    const float* b_f1  = (const float*)d_in[23];
    const float* b_i1  = (const float*)d_in[24];
    const float* b_C1  = (const float*)d_in[25];
    const float* b_o1  = (const float*)d_in[26];
    const float* b_out = (const float*)d_in[27];
    float* out = (float*)d_out;
    (void)W_ih1; (void)n_in; (void)in_sizes; (void)out_size;

    __half *E, *H, *H1, *B0, *B1, *R0, *R1, *hz;
    float *XG0, *XG1, *b0, *b1, *h1f;
    unsigned *pflags;
    cudaGetSymbolAddress((void**)&E,  g_E);
    cudaGetSymbolAddress((void**)&H,  g_H);
    cudaGetSymbolAddress((void**)&H1, g_H1);
    cudaGetSymbolAddress((void**)&B0, g_B0);
    cudaGetSymbolAddress((void**)&B1, g_B1);
    cudaGetSymbolAddress((void**)&R0, g_R0);
    cudaGetSymbolAddress((void**)&R1, g_R1);
    cudaGetSymbolAddress((void**)&XG0, g_XG0);
    cudaGetSymbolAddress((void**)&XG1, g_XG1);
    cudaGetSymbolAddress((void**)&b0, g_b0);
    cudaGetSymbolAddress((void**)&b1, g_b1);
    cudaGetSymbolAddress((void**)&hz,  g_hz);
    cudaGetSymbolAddress((void**)&h1f, g_h1f);
    cudaGetSymbolAddress((void**)&pflags, g_pflags);

    cudaFuncSetAttribute(lstm_persist,
                         cudaFuncAttributeMaxDynamicSharedMemorySize, SM_PERSIST);
    cudaFuncSetAttribute(mm_mma,
                         cudaFuncAttributeMaxDynamicSharedMemorySize, MM_SMEM);

    // All 16 weight conversions in one launch
    WcvtArgs wa;
    const float* srcs[16] = {W_fx, W_ix, W_Cx, W_ox,
                             W_fx1, W_ix1, W_Cx1, W_ox1,
                             W_fh,  W_ih,  W_Ch,  W_oh,
                             W_fh1, W_ih,  W_Ch1, W_oh1};  // layer1 i-gate = W_ih (ref bug)
    for (int z = 0; z < 16; z++) {
        wa.src[z] = srcs[z];
        wa.g[z] = z & 3;
        if (z < 4)       { wa.dst[z] = B0; wa.K[z] = EMB; }
        else if (z < 8)  { wa.dst[z] = B1; wa.K[z] = HID; }
        else if (z < 12) { wa.dst[z] = R0; wa.K[z] = HID; }
        else             { wa.dst[z] = R1; wa.K[z] = HID; }
    }
    wcvt_all<<<dim3(32, 32, 16), dim3(32, 8)>>>(wa);

    pack_b4<<<(HID + 255)/256, 256>>>(b_f,  b_i,  b_C,  b_o,  (float4*)b0);
    pack_b4<<<(HID + 255)/256, 256>>>(b_f1, b_i1, b_C1, b_o1, (float4*)b1);

    zero_init<<<(BATCH*HID + 255)/256, 256>>>(hz, pflags);
    embed_f16<<<(ROWS*EMB + 255)/256, 256>>>(X, Cemb, E);

    // XG0 = E @ Wx0 (fp16 HMMA, pipelined)
    mm_mma<<<dim3(G4/64, ROWS/128), 256, MM_SMEM>>>(E, B0, XG0, EMB);

    // Layer 0 recurrence: persistent, flat-barrier steps
    lstm_persist<<<128, 256, SM_PERSIST>>>(R0, XG0, b0, hz, H, nullptr,
                                           pflags);

    // XG1 = H @ Wx1 (fp16 HMMA, pipelined)
    mm_mma<<<dim3(G4/64, ROWS/128), 256, MM_SMEM>>>(H, B1, XG1, HID);

    // Layer 1 recurrence
    lstm_persist<<<128, 256, SM_PERSIST>>>(R1, XG1, b1, hz, H1, h1f,
                                           pflags + 128*8);

    // out = h1 @ W_out + b_out
    sgemm_out<<<dim3((N_CLASS + 63)/64, 1), 256>>>(h1f, W_out, out,
                                                   N_CLASS, HID, b_out);
}

// round 11
// speedup vs baseline: 1.1555x; 1.1555x over previous
#include <cuda_runtime.h>
#include <cuda_fp16.h>
#include <cstdint>
#include <math.h>

// ---------------------------------------------------------------------------
// Problem constants
// ---------------------------------------------------------------------------
#define N_CLASS 10000
#define EMB     512
#define HID     1024
#define BATCH   64
#define SEQ     128
#define G4      (4*HID)          // 4096 gate columns (interleaved J = 4u+g)
#define ROWS    (SEQ*BATCH)      // 8192

// ---------------------------------------------------------------------------
// mma.sync / ldmatrix / cp.async helpers (arch-portable sm_80+ path)
// ---------------------------------------------------------------------------
__device__ __forceinline__ uint32_t smem_u32(const void* p) {
    uint32_t a;
    asm("{ .reg .u64 t; cvta.to.shared.u64 t, %1; cvt.u32.u64 %0, t; }"
        : "=r"(a) : "l"(p));
    return a;
}

__device__ __forceinline__ void ldmatrix_x4(uint32_t* r, uint32_t addr) {
    asm volatile("ldmatrix.sync.aligned.m8n8.x4.shared.b16 {%0,%1,%2,%3}, [%4];"
                 : "=r"(r[0]), "=r"(r[1]), "=r"(r[2]), "=r"(r[3]) : "r"(addr));
}

// D(f32) += A(f16) * B(f16), m16n8k16, A row-major, B col-major
__device__ __forceinline__ void mma16816(float* d, const uint32_t* a,
                                         const uint32_t* b) {
    asm volatile(
        "mma.sync.aligned.m16n8k16.row.col.f32.f16.f16.f32 "
        "{%0,%1,%2,%3}, {%4,%5,%6,%7}, {%8,%9}, {%0,%1,%2,%3};"
        : "+f"(d[0]), "+f"(d[1]), "+f"(d[2]), "+f"(d[3])
        : "r"(a[0]), "r"(a[1]), "r"(a[2]), "r"(a[3]),
          "r"(b[0]), "r"(b[1]));
}

__device__ __forceinline__ void cpa16(uint32_t s, const void* g) {
    asm volatile("cp.async.cg.shared.global [%0], [%1], 16;" :: "r"(s), "l"(g));
}
__device__ __forceinline__ void cpa_commit() {
    asm volatile("cp.async.commit_group;");
}
template<int N> __device__ __forceinline__ void cpa_wait() {
    asm volatile("cp.async.wait_group %0;" :: "n"(N));
}

__device__ __forceinline__ void st_release(unsigned* p, unsigned v) {
    asm volatile("st.release.gpu.u32 [%0], %1;" :: "l"(p), "r"(v) : "memory");
}
__device__ __forceinline__ unsigned ld_acquire(const unsigned* p) {
    unsigned v;
    asm volatile("ld.acquire.gpu.u32 %0, [%1];" : "=r"(v) : "l"(p) : "memory");
    return v;
}

// Hardware-approx activations (sm_75+)
__device__ __forceinline__ float fast_tanh(float x) {
    float r;
    asm("tanh.approx.f32 %0, %1;" : "=f"(r) : "f"(x));
    return r;
}
__device__ __forceinline__ float fast_sig(float x) {
    float e;
    asm("ex2.approx.f32 %0, %1;" : "=f"(e) : "f"(-1.4426950408889634f * x));
    float r;
    asm("rcp.approx.f32 %0, %1;" : "=f"(r) : "f"(1.0f + e));
    return r;
}

// ---------------------------------------------------------------------------
// Device scratch (static; no cudaMalloc allowed)
// ---------------------------------------------------------------------------
__device__ __half g_E  [ROWS*EMB];      // embeddings fp16, row = t*64+b
__device__ __half g_H  [ROWS*HID];      // layer0 h: [t][m][u] fp16
__device__ __half g_H1 [ROWS*HID];      // layer1 h: [t][m][u] fp16
__device__ __half g_B0 [G4*EMB];        // input weights L0 [J=4u+g][k]
__device__ __half g_B1 [G4*HID];        // input weights L1
__device__ __half g_R0 [G4*HID];        // recurrent weights L0 [J][k]
__device__ __half g_R1 [G4*HID];        // recurrent weights L1
__device__ float g_XG0[ROWS*G4];
__device__ float g_XG1[ROWS*G4];
__device__ float g_b0 [G4];
__device__ float g_b1 [G4];
__device__ __half g_hz [BATCH*HID];     // zero h
__device__ float g_h1f [BATCH*HID];     // layer1 final h fp32
__device__ unsigned g_pflags[2*128*8];  // per-block step flags (x8 padded)

// ---------------------------------------------------------------------------
// Prep kernels
// ---------------------------------------------------------------------------
struct WcvtArgs {
    const float* src[16];
    __half* dst[16];
    int K[16];
    int g[16];
};

// W[K][1024](fp32, col u) -> dst[4u+g][K] fp16; one launch for all 16 mats.
__global__ void wcvt_all(WcvtArgs a)
{
    __shared__ float s[32][33];
    const int z = blockIdx.z;
    const int K = a.K[z];
    const int k0 = blockIdx.x * 32;
    if (k0 >= K) return;
    const float* W = a.src[z];
    __half* B = a.dst[z];
    const int g = a.g[z];
    const int u0 = blockIdx.y * 32;
    const int tx = threadIdx.x, ty = threadIdx.y;        // (32, 8)
#pragma unroll
    for (int j = 0; j < 4; j++)
        s[ty + j*8][tx] = W[(size_t)(k0 + ty + j*8) * HID + u0 + tx];
    __syncthreads();
#pragma unroll
    for (int j = 0; j < 4; j++) {
        int uu = ty + j*8;
        B[(size_t)(4*(u0 + uu) + g) * K + k0 + tx] = __float2half(s[tx][uu]);
    }
}

__global__ void pack_b4(const float* __restrict__ a, const float* __restrict__ b,
                        const float* __restrict__ c, const float* __restrict__ d,
                        float4* __restrict__ dst)
{
    int u = blockIdx.x * blockDim.x + threadIdx.x;
    if (u < HID) dst[u] = make_float4(a[u], b[u], c[u], d[u]);
}

__global__ void zero_init(__half* __restrict__ hz,
                          unsigned* __restrict__ pflags)
{
    int idx = blockIdx.x * blockDim.x + threadIdx.x;
    if (idx < BATCH * HID) hz[idx] = __float2half(0.f);
    if (idx < 2*128*8) pflags[idx] = 0;
}

__global__ void embed_f16(const int* __restrict__ X, const float* __restrict__ C,
                          __half* __restrict__ E)
{
    int idx = blockIdx.x * blockDim.x + threadIdx.x;
    if (idx < ROWS * EMB) {
        int row = idx >> 9, e = idx & 511;
        int t = row >> 6, b = row & 63;
        int tok = X[b * SEQ + t];
        E[idx] = __float2half(C[(size_t)tok * EMB + e]);
    }
}

// ---------------------------------------------------------------------------
// HMMA fp16 GEMM with 3-stage cp.async ring (2-chunk lookahead covers L2
// latency): C[M][4096] = A[M][K] @ B[4096][K]^T, 128x64 tile, 256 thr.
// Stage: [0,10240) A (128 rows x 80B), [10240,15360) B (64 rows x 80B).
// ---------------------------------------------------------------------------
#define MM_STAGE 15360
#define MM_SMEM  (3*MM_STAGE)
__global__ __launch_bounds__(256)
void mm_mma(const __half* __restrict__ Ag, const __half* __restrict__ Bg,
            float* __restrict__ Cm, int K)
{
    extern __shared__ __align__(16) char smc[];
    const int tid = threadIdx.x, lane = tid & 31, w = tid >> 5;
    const int m0 = blockIdx.y * 128, n0 = blockIdx.x * 64;
    const int wm = (w & 3) * 32, wn = (w >> 2) * 32;
    const int g = lane >> 2, tig = lane & 3;
    const int sub = lane >> 3, lr = lane & 7;
    const uint32_t sbase = smem_u32(smc);

    float acc[2][4][4];
#pragma unroll
    for (int ti = 0; ti < 2; ti++)
#pragma unroll
        for (int j = 0; j < 4; j++)
#pragma unroll
            for (int q = 0; q < 4; q++) acc[ti][j][q] = 0.f;

    uint32_t aOff[2];
#pragma unroll
    for (int ti = 0; ti < 2; ti++)
        aOff[ti] = (wm + ti*16 + (sub & 1)*8 + lr)*80 + (sub >> 1)*16;

    const int ar = tid >> 2, as4 = tid & 3;

    auto issue = [&](int c) {
        uint32_t base = sbase + (c % 3) * MM_STAGE;
        size_t kb = (size_t)c * 32;
#pragma unroll
        for (int i = 0; i < 2; i++) {
            int r = ar + i * 64;
            cpa16(base + r*80 + as4*16, Ag + (size_t)(m0 + r) * K + kb + as4*8);
        }
        cpa16(base + 10240 + ar*80 + as4*16,
              Bg + (size_t)(n0 + ar) * K + kb + as4*8);
        cpa_commit();
    };

    const int nchunk = K >> 5;
    issue(0);
    if (nchunk > 1) issue(1);
    for (int c = 0; c < nchunk; c++) {
        __syncthreads();                 // stage (c+2)%3 reads (from iter c-1) done
        if (c + 2 < nchunk) issue(c + 2);
        // chunk c complete when pending <= (#issued - (c+1))
        if (c + 2 < nchunk)      cpa_wait<2>();
        else if (c + 1 < nchunk) cpa_wait<1>();
        else                     cpa_wait<0>();
        __syncthreads();                 // cp.async data visible to all

        const uint32_t st = sbase + (c % 3) * MM_STAGE;
        const uint32_t stRel = (c % 3) * MM_STAGE;
#pragma unroll
        for (int ks = 0; ks < 2; ks++) {
            uint32_t a[2][4];
#pragma unroll
            for (int ti = 0; ti < 2; ti++)
                ldmatrix_x4(a[ti], st + aOff[ti] + ks*32);
            uint32_t bh[4][2];
#pragma unroll
            for (int j = 0; j < 4; j++) {
                uint32_t off = stRel + 10240 + (wn + 8*j + g)*80 + ks*32 + tig*4;
                bh[j][0] = *(const uint32_t*)(smc + off);
                bh[j][1] = *(const uint32_t*)(smc + off + 16);
            }
#pragma unroll
            for (int ti = 0; ti < 2; ti++)
#pragma unroll
                for (int j = 0; j < 4; j++)
                    mma16816(acc[ti][j], a[ti], bh[j]);
        }
    }

#pragma unroll
    for (int ti = 0; ti < 2; ti++) {
        int row = m0 + wm + ti*16 + g;
#pragma unroll
        for (int j = 0; j < 4; j++) {
            int col = n0 + wn + 8*j + tig*2;
            *(float2*)&Cm[(size_t)row * G4 + col] =
                make_float2(acc[ti][j][0], acc[ti][j][1]);
            *(float2*)&Cm[(size_t)(row + 8) * G4 + col] =
                make_float2(acc[ti][j][2], acc[ti][j][3]);
        }
    }
}

// ---------------------------------------------------------------------------
// Persistent LSTM recurrence kernel (fp16, whole-h in smem, round-9 base).
// 128 blocks x 256 thr. Block owns 32 gate columns; weight slice (32x1024
// fp16 = 66KB) + TWO h-halves in smem. h streamed as FOUR 16KB cp.async
// quarter-groups (wait_group 3/2/1/0) so the first MMA starts after 16KB,
// not 64KB. Flat ONE-HOP grid barrier (unchanged from round 9).
// ---------------------------------------------------------------------------
#define PW 2064                       // weight smem row pitch (2048 + 16 pad)
#define PAH 1040                      // A-half row pitch (1024 + 16 pad)
#define W_BYTES (32*PW)               // 66048
#define A_HALF (64*PAH)               // 66560
#define A_OFF   W_BYTES
#define SM_PERSIST (A_OFF + 2*A_HALF) // 199168

__global__ __launch_bounds__(256, 1)
void lstm_persist(const __half* __restrict__ Wg,
                  const float* __restrict__ XG, const float* __restrict__ bias,
                  const __half* __restrict__ hz,
                  __half* __restrict__ Hout,        // [SEQ][64][1024]
                  float* __restrict__ hf,
                  unsigned* __restrict__ pflags)    // [128] x8-padded
{
    extern __shared__ __align__(16) char sm[];
    char* sW = sm;
    const uint32_t aAbs = smem_u32(sm) + A_OFF;

    const int tid = threadIdx.x, lane = tid & 31, w = tid >> 5;
    const int wr = w & 3, wc = w >> 2;
    const int g = lane >> 2, tig = lane & 3;
    const int sub = lane >> 3, lr = lane & 7;
    const int n0 = blockIdx.x * 32;

    // ---- load this block's weight slice into smem (once) ----
    for (int idx = tid; idx < 4096; idx += 256) {
        int r = idx >> 7, s = idx & 127;
        *(uint4*)(sW + r*PW + s*16) =
            *(const uint4*)(Wg + ((size_t)(n0 + r) << 10) + s*8);
    }
    __syncthreads();

    const uint32_t rowoff = (16*wr + (sub & 1)*8 + lr)*PAH + (sub >> 1)*16;
    const int brow0 = (wc*16 + g)*PW;
    const int brow1 = (wc*16 + 8 + g)*PW;
    const int m1 = 16*wr + g, m2 = m1 + 8;
    const int Jc0 = n0 + wc*16 + tig*2;
    const int Jc1 = Jc0 + 8;
    const float2 bb0 = *(const float2*)&bias[Jc0];
    const float2 bb1 = *(const float2*)&bias[Jc1];
    const bool co = (tig & 1);
    const int u0 = Jc0 >> 2, u1 = Jc1 >> 2;

    float cc00 = 0.f, cc01 = 0.f, cc10 = 0.f, cc11 = 0.f;

    for (int t = 0; t < SEQ; t++) {
        const __half* ph = t ? (Hout + (size_t)(t-1) * BATCH * HID) : hz;
        __half* dh = Hout + (size_t)t * BATCH * HID;

        // prefetch xg for this step (independent of the recurrence chain)
        const float* xb = XG + (((size_t)(t*64)) << 12);
        const float2 x1_0 = *(const float2*)(xb + (size_t)m1*G4 + Jc0);
        const float2 x2_0 = *(const float2*)(xb + (size_t)m2*G4 + Jc0);
        const float2 x1_1 = *(const float2*)(xb + (size_t)m1*G4 + Jc1);
        const float2 x2_1 = *(const float2*)(xb + (size_t)m2*G4 + Jc1);

        // issue one 64x256-col quarter (16 KB) of h_prev; quarter q lives in
        // half (q>>1) at byte offset (q&1)*512 within each 1024B row span.
        auto issueQ = [&](int q) {
            uint32_t dst = aAbs + (q >> 1) * A_HALF + (q & 1) * 512;
            const __half* src = ph + q * 256;
#pragma unroll
            for (int i = 0; i < 8; i++) {
                int lin = tid + i * 256;          // 0..2047
                int r = lin >> 5, s = lin & 31;
                cpa16(dst + r*PAH + s*16, src + ((size_t)r << 10) + s*8);
            }
            cpa_commit();
        };

        issueQ(0); issueQ(1); issueQ(2); issueQ(3);

        float acc0[4] = {0.f, 0.f, 0.f, 0.f};
        float acc1[4] = {0.f, 0.f, 0.f, 0.f};

#pragma unroll
        for (int q = 0; q < 4; q++) {
            if (q == 0)      cpa_wait<3>();
            else if (q == 1) cpa_wait<2>();
            else if (q == 2) cpa_wait<1>();
            else             cpa_wait<0>();
            __syncthreads();
            const uint32_t ah = aAbs + (q >> 1) * A_HALF + (q & 1) * 512 + rowoff;
            const int kbase = q * 512;     // byte offset into weight row
#pragma unroll 8
            for (int ks = 0; ks < 16; ks++) {
                uint32_t a0[4];
                ldmatrix_x4(a0, ah + ks*32);
                const int ko = kbase + ks*32 + tig*4;
                uint32_t b0[2], b1[2];
                b0[0] = *(const uint32_t*)(sW + brow0 + ko);
                b0[1] = *(const uint32_t*)(sW + brow0 + ko + 16);
                b1[0] = *(const uint32_t*)(sW + brow1 + ko);
                b1[1] = *(const uint32_t*)(sW + brow1 + ko + 16);
                mma16816(acc0, a0, b0);
                mma16816(acc1, a0, b1);
            }
        }

        // ---- pointwise epilogue (hardware-approx activations) ----
        {
            float p0 = acc0[0] + x1_0.x + bb0.x;
            float p1 = acc0[1] + x1_0.y + bb0.y;
            float p2 = acc0[2] + x2_0.x + bb0.x;
            float p3 = acc0[3] + x2_0.y + bb0.y;
            float a0v = co ? fast_tanh(p0) : fast_sig(p0);
            float a1v = fast_sig(p1);
            float a2v = co ? fast_tanh(p2) : fast_sig(p2);
            float a3v = fast_sig(p3);
            float C1 = __shfl_xor_sync(0xFFFFFFFFu, a0v, 1);
            float O1 = __shfl_xor_sync(0xFFFFFFFFu, a1v, 1);
            float C2 = __shfl_xor_sync(0xFFFFFFFFu, a2v, 1);
            float O2 = __shfl_xor_sync(0xFFFFFFFFu, a3v, 1);
            if (!co) {
                cc00 = a0v * cc00 + a1v * C1;
                float hv = O1 * fast_tanh(cc00);
                dh[m1*HID + u0] = __float2half(hv);
                if (hf && t == SEQ-1) hf[m1*HID + u0] = hv;
                cc01 = a2v * cc01 + a3v * C2;
                hv = O2 * fast_tanh(cc01);
                dh[m2*HID + u0] = __float2half(hv);
                if (hf && t == SEQ-1) hf[m2*HID + u0] = hv;
            }
        }
        {
            float p0 = acc1[0] + x1_1.x + bb1.x;
            float p1 = acc1[1] + x1_1.y + bb1.y;
            float p2 = acc1[2] + x2_1.x + bb1.x;
            float p3 = acc1[3] + x2_1.y + bb1.y;
            float a0v = co ? fast_tanh(p0) : fast_sig(p0);
            float a1v = fast_sig(p1);
            float a2v = co ? fast_tanh(p2) : fast_sig(p2);
            float a3v = fast_sig(p3);
            float C1 = __shfl_xor_sync(0xFFFFFFFFu, a0v, 1);
            float O1 = __shfl_xor_sync(0xFFFFFFFFu, a1v, 1);
            float C2 = __shfl_xor_sync(0xFFFFFFFFu, a2v, 1);
            float O2 = __shfl_xor_sync(0xFFFFFFFFu, a3v, 1);
            if (!co) {
                cc10 = a0v * cc10 + a1v * C1;
                float hv = O1 * fast_tanh(cc10);
                dh[m1*HID + u1] = __float2half(hv);
                if (hf && t == SEQ-1) hf[m1*HID + u1] = hv;
                cc11 = a2v * cc11 + a3v * C2;
                hv = O2 * fast_tanh(cc11);
                dh[m2*HID + u1] = __float2half(hv);
                if (hf && t == SEQ-1) hf[m2*HID + u1] = hv;
            }
        }

        // ---- flat one-hop grid barrier (skip after last step) ----
        if (t != SEQ-1) {
            const unsigned sense = (unsigned)(t + 1);
            __syncthreads();              // all h stores in this block done
            if (tid == 0)
                st_release(pflags + blockIdx.x*8, sense);
            if (tid < 128) {
                const unsigned* f = pflags + tid*8;
                while (ld_acquire(f) < sense) {}
            }
            __syncthreads();
        }
    }
}

// ---------------------------------------------------------------------------
// Output projection: out[64][N] = A[64][K] @ B[K][N] + bias (fp32)
// ---------------------------------------------------------------------------
__global__ __launch_bounds__(256)
void sgemm_out(const float* __restrict__ A, const float* __restrict__ B,
               float* __restrict__ Cmat, int N, int K, const float* __restrict__ bias)
{
    __shared__ __align__(16) float As[16][68];
    __shared__ __align__(16) float Bs[16][68];

    const int tid = threadIdx.x;
    const int tx = tid & 15, ty = tid >> 4;
    const int n0 = blockIdx.x * 64;

    float acc[4][4];
#pragma unroll
    for (int r = 0; r < 4; r++)
#pragma unroll
        for (int c = 0; c < 4; c++) acc[r][c] = 0.f;

    const int am = tid >> 2;
    const int akg = tid & 3;
    const int bk = tid >> 4;
    const int bn4 = tid & 15;

    for (int k0 = 0; k0 < K; k0 += 16) {
        float4 av = *(const float4*)&A[(size_t)am * K + k0 + akg * 4];
        float4 bv;
        if (n0 + bn4 * 4 < N)
            bv = *(const float4*)&B[(size_t)(k0 + bk) * N + n0 + bn4 * 4];
        else
            bv = make_float4(0.f, 0.f, 0.f, 0.f);
        As[akg*4 + 0][am] = av.x;
        As[akg*4 + 1][am] = av.y;
        As[akg*4 + 2][am] = av.z;
        As[akg*4 + 3][am] = av.w;
        *(float4*)&Bs[bk][bn4 * 4] = bv;
        __syncthreads();
#pragma unroll
        for (int kk = 0; kk < 16; kk++) {
            float4 a4 = *(const float4*)&As[kk][ty * 4];
            float4 b4 = *(const float4*)&Bs[kk][tx * 4];
            acc[0][0] = fmaf(a4.x, b4.x, acc[0][0]);
            acc[0][1] = fmaf(a4.x, b4.y, acc[0][1]);
            acc[0][2] = fmaf(a4.x, b4.z, acc[0][2]);
            acc[0][3] = fmaf(a4.x, b4.w, acc[0][3]);
            acc[1][0] = fmaf(a4.y, b4.x, acc[1][0]);
            acc[1][1] = fmaf(a4.y, b4.y, acc[1][1]);
            acc[1][2] = fmaf(a4.y, b4.z, acc[1][2]);
            acc[1][3] = fmaf(a4.y, b4.w, acc[1][3]);
            acc[2][0] = fmaf(a4.z, b4.x, acc[2][0]);
            acc[2][1] = fmaf(a4.z, b4.y, acc[2][1]);
            acc[2][2] = fmaf(a4.z, b4.z, acc[2][2]);
            acc[2][3] = fmaf(a4.z, b4.w, acc[2][3]);
            acc[3][0] = fmaf(a4.w, b4.x, acc[3][0]);
            acc[3][1] = fmaf(a4.w, b4.y, acc[3][1]);
            acc[3][2] = fmaf(a4.w, b4.z, acc[3][2]);
            acc[3][3] = fmaf(a4.w, b4.w, acc[3][3]);
        }
        __syncthreads();
    }

#pragma unroll
    for (int r = 0; r < 4; r++) {
        int m = ty * 4 + r;
#pragma unroll
        for (int c = 0; c < 4; c++) {
            int n = n0 + tx * 4 + c;
            if (n < N) Cmat[(size_t)m * N + n] = acc[r][c] + bias[n];
        }
    }
}

// ---------------------------------------------------------------------------
// Host launcher (graph-capturable: kernel launches only)
// ---------------------------------------------------------------------------
extern "C" void kernel_launch(void* const* d_in, const int* in_sizes, int n_in,
                              void* d_out, int out_size)
{
    const int*   X     = (const int*)  d_in[0];
    const float* Cemb  = (const float*)d_in[1];
    const float* W_fx  = (const float*)d_in[2];
    const float* W_fh  = (const float*)d_in[3];
    const float* W_ix  = (const float*)d_in[4];
    const float* W_ih  = (const float*)d_in[5];
    const float* W_Cx  = (const float*)d_in[6];
    const float* W_Ch  = (const float*)d_in[7];
    const float* W_ox  = (const float*)d_in[8];
    const float* W_oh  = (const float*)d_in[9];
    const float* W_fx1 = (const float*)d_in[10];
    const float* W_fh1 = (const float*)d_in[11];
    const float* W_ix1 = (const float*)d_in[12];
    const float* W_ih1 = (const float*)d_in[13];   // unused (reference bug kept)
    const float* W_Cx1 = (const float*)d_in[14];
    const float* W_Ch1 = (const float*)d_in[15];
    const float* W_ox1 = (const float*)d_in[16];
    const float* W_oh1 = (const float*)d_in[17];
    const float* W_out = (const float*)d_in[18];
    const float* b_f   = (const float*)d_in[19];
    const float* b_i   = (const float*)d_in[20];
    const float* b_C   = (const float*)d_in[21];
    const float* b_o   = (const float*)d_in[22];
    const float* b_f1  = (const float*)d_in[23];
    const float* b_i1  = (const float*)d_in[24];
    const float* b_C1  = (const float*)d_in[25];
    const float* b_o1  = (const float*)d_in[26];
    const float* b_out = (const float*)d_in[27];
    float* out = (float*)d_out;
    (void)W_ih1; (void)n_in; (void)in_sizes; (void)out_size;

    __half *E, *H, *H1, *B0, *B1, *R0, *R1, *hz;
    float *XG0, *XG1, *b0, *b1, *h1f;
    unsigned *pflags;
    cudaGetSymbolAddress((void**)&E,  g_E);
    cudaGetSymbolAddress((void**)&H,  g_H);
    cudaGetSymbolAddress((void**)&H1, g_H1);
    cudaGetSymbolAddress((void**)&B0, g_B0);
    cudaGetSymbolAddress((void**)&B1, g_B1);
    cudaGetSymbolAddress((void**)&R0, g_R0);
    cudaGetSymbolAddress((void**)&R1, g_R1);
    cudaGetSymbolAddress((void**)&XG0, g_XG0);
    cudaGetSymbolAddress((void**)&XG1, g_XG1);
    cudaGetSymbolAddress((void**)&b0, g_b0);
    cudaGetSymbolAddress((void**)&b1, g_b1);
    cudaGetSymbolAddress((void**)&hz,  g_hz);
    cudaGetSymbolAddress((void**)&h1f, g_h1f);
    cudaGetSymbolAddress((void**)&pflags, g_pflags);

    cudaFuncSetAttribute(lstm_persist,
                         cudaFuncAttributeMaxDynamicSharedMemorySize, SM_PERSIST);
    cudaFuncSetAttribute(mm_mma,
                         cudaFuncAttributeMaxDynamicSharedMemorySize, MM_SMEM);

    // All 16 weight conversions in one launch
    WcvtArgs wa;
    const float* srcs[16] = {W_fx, W_ix, W_Cx, W_ox,
                             W_fx1, W_ix1, W_Cx1, W_ox1,
                             W_fh,  W_ih,  W_Ch,  W_oh,
                             W_fh1, W_ih,  W_Ch1, W_oh1};  // layer1 i-gate = W_ih (ref bug)
    for (int z = 0; z < 16; z++) {
        wa.src[z] = srcs[z];
        wa.g[z] = z & 3;
        if (z < 4)       { wa.dst[z] = B0; wa.K[z] = EMB; }
        else if (z < 8)  { wa.dst[z] = B1; wa.K[z] = HID; }
        else if (z < 12) { wa.dst[z] = R0; wa.K[z] = HID; }
        else             { wa.dst[z] = R1; wa.K[z] = HID; }
    }
    wcvt_all<<<dim3(32, 32, 16), dim3(32, 8)>>>(wa);

    pack_b4<<<(HID + 255)/256, 256>>>(b_f,  b_i,  b_C,  b_o,  (float4*)b0);
    pack_b4<<<(HID + 255)/256, 256>>>(b_f1, b_i1, b_C1, b_o1, (float4*)b1);

    zero_init<<<(BATCH*HID + 255)/256, 256>>>(hz, pflags);
    embed_f16<<<(ROWS*EMB + 255)/256, 256>>>(X, Cemb, E);

    // XG0 = E @ Wx0 (fp16 HMMA, 3-stage pipeline)
    mm_mma<<<dim3(G4/64, ROWS/128), 256, MM_SMEM>>>(E, B0, XG0, EMB);

    // Layer 0 recurrence: persistent, flat-barrier steps
    lstm_persist<<<128, 256, SM_PERSIST>>>(R0, XG0, b0, hz, H, nullptr,
                                           pflags);

    // XG1 = H @ Wx1 (fp16 HMMA, 3-stage pipeline)
    mm_mma<<<dim3(G4/64, ROWS/128), 256, MM_SMEM>>>(H, B1, XG1, HID);

    // Layer 1 recurrence
    lstm_persist<<<128, 256, SM_PERSIST>>>(R1, XG1, b1, hz, H1, h1f,
                                           pflags + 128*8);

    // out = h1 @ W_out + b_out
    sgemm_out<<<dim3((N_CLASS + 63)/64, 1), 256>>>(h1f, W_out, out,
                                                   N_CLASS, HID, b_out);
}

// round 12
// speedup vs baseline: 1.2471x; 1.0793x over previous
#include <cuda_runtime.h>
#include <cuda_fp16.h>
#include <cstdint>
#include <math.h>

// ---------------------------------------------------------------------------
// Problem constants
// ---------------------------------------------------------------------------
#define N_CLASS 10000
#define EMB     512
#define HID     1024
#define BATCH   64
#define SEQ     128
#define G4      (4*HID)          // 4096 gate columns (interleaved J = 4u+g)
#define ROWS    (SEQ*BATCH)      // 8192

// ---------------------------------------------------------------------------
// mma.sync / ldmatrix / cp.async(+bulk) helpers (sm_90-base ISA, no 'a' feats)
// ---------------------------------------------------------------------------
__device__ __forceinline__ uint32_t smem_u32(const void* p) {
    uint32_t a;
    asm("{ .reg .u64 t; cvta.to.shared.u64 t, %1; cvt.u32.u64 %0, t; }"
        : "=r"(a) : "l"(p));
    return a;
}

__device__ __forceinline__ void ldmatrix_x4(uint32_t* r, uint32_t addr) {
    asm volatile("ldmatrix.sync.aligned.m8n8.x4.shared.b16 {%0,%1,%2,%3}, [%4];"
                 : "=r"(r[0]), "=r"(r[1]), "=r"(r[2]), "=r"(r[3]) : "r"(addr));
}

// D(f32) += A(f16) * B(f16), m16n8k16, A row-major, B col-major
__device__ __forceinline__ void mma16816(float* d, const uint32_t* a,
                                         const uint32_t* b) {
    asm volatile(
        "mma.sync.aligned.m16n8k16.row.col.f32.f16.f16.f32 "
        "{%0,%1,%2,%3}, {%4,%5,%6,%7}, {%8,%9}, {%0,%1,%2,%3};"
        : "+f"(d[0]), "+f"(d[1]), "+f"(d[2]), "+f"(d[3])
        : "r"(a[0]), "r"(a[1]), "r"(a[2]), "r"(a[3]),
          "r"(b[0]), "r"(b[1]));
}

__device__ __forceinline__ void cpa16(uint32_t s, const void* g) {
    asm volatile("cp.async.cg.shared.global [%0], [%1], 16;" :: "r"(s), "l"(g));
}
__device__ __forceinline__ void cpa_commit() {
    asm volatile("cp.async.commit_group;");
}
template<int N> __device__ __forceinline__ void cpa_wait() {
    asm volatile("cp.async.wait_group %0;" :: "n"(N));
}

// Bulk async copy global->shared with mbarrier completion (sm_90 base)
__device__ __forceinline__ void cpa_bulk(uint32_t dst, const void* src,
                                         uint32_t bytes, uint32_t mbar) {
    asm volatile(
        "cp.async.bulk.shared::cta.global.mbarrier::complete_tx::bytes "
        "[%0], [%1], %2, [%3];"
        :: "r"(dst), "l"(src), "r"(bytes), "r"(mbar) : "memory");
}
__device__ __forceinline__ void mbar_init(uint32_t mbar, uint32_t cnt) {
    asm volatile("mbarrier.init.shared.b64 [%0], %1;" :: "r"(mbar), "r"(cnt)
                 : "memory");
}
__device__ __forceinline__ void mbar_expect_tx(uint32_t mbar, uint32_t bytes) {
    asm volatile("mbarrier.arrive.expect_tx.shared.b64 _, [%0], %1;"
                 :: "r"(mbar), "r"(bytes) : "memory");
}
__device__ __forceinline__ void mbar_wait(uint32_t mbar, uint32_t parity) {
    uint32_t done;
    asm volatile(
        "{\n\t.reg .pred p;\n\t"
        "mbarrier.try_wait.parity.acquire.cta.shared::cta.b64 p, [%1], %2;\n\t"
        "selp.b32 %0, 1, 0, p;\n\t}"
        : "=r"(done) : "r"(mbar), "r"(parity) : "memory");
    if (!done) {
        asm volatile(
            "{\n\t.reg .pred P1;\n\t"
            "WL_%=:\n\t"
            "mbarrier.try_wait.parity.acquire.cta.shared::cta.b64 P1, [%0], %1, 0x989680;\n\t"
            "@P1 bra.uni WD_%=;\n\t"
            "bra.uni WL_%=;\n\t"
            "WD_%=:\n\t}"
            :: "r"(mbar), "r"(parity) : "memory");
    }
}
__device__ __forceinline__ void fence_proxy_async_cta() {
    asm volatile("fence.proxy.async.shared::cta;" ::: "memory");
}

__device__ __forceinline__ void st_release(unsigned* p, unsigned v) {
    asm volatile("st.release.gpu.u32 [%0], %1;" :: "l"(p), "r"(v) : "memory");
}
__device__ __forceinline__ unsigned ld_acquire(const unsigned* p) {
    unsigned v;
    asm volatile("ld.acquire.gpu.u32 %0, [%1];" : "=r"(v) : "l"(p) : "memory");
    return v;
}

// Hardware-approx activations (sm_75+)
__device__ __forceinline__ float fast_tanh(float x) {
    float r;
    asm("tanh.approx.f32 %0, %1;" : "=f"(r) : "f"(x));
    return r;
}
__device__ __forceinline__ float fast_sig(float x) {
    float e;
    asm("ex2.approx.f32 %0, %1;" : "=f"(e) : "f"(-1.4426950408889634f * x));
    float r;
    asm("rcp.approx.f32 %0, %1;" : "=f"(r) : "f"(1.0f + e));
    return r;
}

// ---------------------------------------------------------------------------
// Device scratch (static; no cudaMalloc allowed)
// ---------------------------------------------------------------------------
__device__ __half g_E   [ROWS*EMB];     // embeddings fp16, row = t*64+b
__device__ __half g_H   [ROWS*HID];     // layer0 h PLAIN [t][m][u] (for XG1)
__device__ __half g_Hsw [ROWS*HID];     // layer0 h SWIZZLED smem-image
__device__ __half g_H1sw[ROWS*HID];     // layer1 h SWIZZLED smem-image
__device__ __half g_B0 [G4*EMB];        // input weights L0 [J=4u+g][k]
__device__ __half g_B1 [G4*HID];        // input weights L1
__device__ __half g_R0 [G4*HID];        // recurrent weights L0 [J][k]
__device__ __half g_R1 [G4*HID];        // recurrent weights L1
__device__ float g_XG0[ROWS*G4];
__device__ float g_XG1[ROWS*G4];
__device__ float g_b0 [G4];
__device__ float g_b1 [G4];
__device__ __half g_hz [BATCH*HID];     // zero h (any layout: zeros)
__device__ float g_h1f [BATCH*HID];     // layer1 final h fp32
__device__ unsigned g_pflags[2*128*8];  // per-block step flags (x8 padded)

// ---------------------------------------------------------------------------
// Prep kernels
// ---------------------------------------------------------------------------
struct WcvtArgs {
    const float* src[16];
    __half* dst[16];
    int K[16];
    int g[16];
};

// W[K][1024](fp32, col u) -> dst[4u+g][K] fp16; one launch for all 16 mats.
__global__ void wcvt_all(WcvtArgs a)
{
    __shared__ float s[32][33];
    const int z = blockIdx.z;
    const int K = a.K[z];
    const int k0 = blockIdx.x * 32;
    if (k0 >= K) return;
    const float* W = a.src[z];
    __half* B = a.dst[z];
    const int g = a.g[z];
    const int u0 = blockIdx.y * 32;
    const int tx = threadIdx.x, ty = threadIdx.y;        // (32, 8)
#pragma unroll
    for (int j = 0; j < 4; j++)
        s[ty + j*8][tx] = W[(size_t)(k0 + ty + j*8) * HID + u0 + tx];
    __syncthreads();
#pragma unroll
    for (int j = 0; j < 4; j++) {
        int uu = ty + j*8;
        B[(size_t)(4*(u0 + uu) + g) * K + k0 + tx] = __float2half(s[tx][uu]);
    }
}

__global__ void pack_b4(const float* __restrict__ a, const float* __restrict__ b,
                        const float* __restrict__ c, const float* __restrict__ d,
                        float4* __restrict__ dst)
{
    int u = blockIdx.x * blockDim.x + threadIdx.x;
    if (u < HID) dst[u] = make_float4(a[u], b[u], c[u], d[u]);
}

__global__ void zero_init(__half* __restrict__ hz,
                          unsigned* __restrict__ pflags)
{
    int idx = blockIdx.x * blockDim.x + threadIdx.x;
    if (idx < BATCH * HID) hz[idx] = __float2half(0.f);
    if (idx < 2*128*8) pflags[idx] = 0;
}

__global__ void embed_f16(const int* __restrict__ X, const float* __restrict__ C,
                          __half* __restrict__ E)
{
    int idx = blockIdx.x * blockDim.x + threadIdx.x;
    if (idx < ROWS * EMB) {
        int row = idx >> 9, e = idx & 511;
        int t = row >> 6, b = row & 63;
        int tok = X[b * SEQ + t];
        E[idx] = __float2half(C[(size_t)tok * EMB + e]);
    }
}

// ---------------------------------------------------------------------------
// HMMA fp16 GEMM with 3-stage cp.async ring (round-11, known good):
// C[M][4096] = A[M][K] @ B[4096][K]^T, 128x64 tile, 256 thr.
// ---------------------------------------------------------------------------
#define MM_STAGE 15360
#define MM_SMEM  (3*MM_STAGE)
__global__ __launch_bounds__(256)
void mm_mma(const __half* __restrict__ Ag, const __half* __restrict__ Bg,
            float* __restrict__ Cm, int K)
{
    extern __shared__ __align__(16) char smc[];
    const int tid = threadIdx.x, lane = tid & 31, w = tid >> 5;
    const int m0 = blockIdx.y * 128, n0 = blockIdx.x * 64;
    const int wm = (w & 3) * 32, wn = (w >> 2) * 32;
    const int g = lane >> 2, tig = lane & 3;
    const int sub = lane >> 3, lr = lane & 7;
    const uint32_t sbase = smem_u32(smc);

    float acc[2][4][4];
#pragma unroll
    for (int ti = 0; ti < 2; ti++)
#pragma unroll
        for (int j = 0; j < 4; j++)
#pragma unroll
            for (int q = 0; q < 4; q++) acc[ti][j][q] = 0.f;

    uint32_t aOff[2];
#pragma unroll
    for (int ti = 0; ti < 2; ti++)
        aOff[ti] = (wm + ti*16 + (sub & 1)*8 + lr)*80 + (sub >> 1)*16;

    const int ar = tid >> 2, as4 = tid & 3;

    auto issue = [&](int c) {
        uint32_t base = sbase + (c % 3) * MM_STAGE;
        size_t kb = (size_t)c * 32;
#pragma unroll
        for (int i = 0; i < 2; i++) {
            int r = ar + i * 64;
            cpa16(base + r*80 + as4*16, Ag + (size_t)(m0 + r) * K + kb + as4*8);
        }
        cpa16(base + 10240 + ar*80 + as4*16,
              Bg + (size_t)(n0 + ar) * K + kb + as4*8);
        cpa_commit();
    };

    const int nchunk = K >> 5;
    issue(0);
    if (nchunk > 1) issue(1);
    for (int c = 0; c < nchunk; c++) {
        __syncthreads();
        if (c + 2 < nchunk) issue(c + 2);
        if (c + 2 < nchunk)      cpa_wait<2>();
        else if (c + 1 < nchunk) cpa_wait<1>();
        else                     cpa_wait<0>();
        __syncthreads();

        const uint32_t st = sbase + (c % 3) * MM_STAGE;
        const uint32_t stRel = (c % 3) * MM_STAGE;
#pragma unroll
        for (int ks = 0; ks < 2; ks++) {
            uint32_t a[2][4];
#pragma unroll
            for (int ti = 0; ti < 2; ti++)
                ldmatrix_x4(a[ti], st + aOff[ti] + ks*32);
            uint32_t bh[4][2];
#pragma unroll
            for (int j = 0; j < 4; j++) {
                uint32_t off = stRel + 10240 + (wn + 8*j + g)*80 + ks*32 + tig*4;
                bh[j][0] = *(const uint32_t*)(smc + off);
                bh[j][1] = *(const uint32_t*)(smc + off + 16);
            }
#pragma unroll
            for (int ti = 0; ti < 2; ti++)
#pragma unroll
                for (int j = 0; j < 4; j++)
                    mma16816(acc[ti][j], a[ti], bh[j]);
        }
    }

#pragma unroll
    for (int ti = 0; ti < 2; ti++) {
        int row = m0 + wm + ti*16 + g;
#pragma unroll
        for (int j = 0; j < 4; j++) {
            int col = n0 + wn + 8*j + tig*2;
            *(float2*)&Cm[(size_t)row * G4 + col] =
                make_float2(acc[ti][j][0], acc[ti][j][1]);
            *(float2*)&Cm[(size_t)(row + 8) * G4 + col] =
                make_float2(acc[ti][j][2], acc[ti][j][3]);
        }
    }
}

// ---------------------------------------------------------------------------
// Persistent LSTM recurrence kernel (fp16, cp.async.bulk h streaming).
// 128 blocks x 256 thr. Block owns 32 gate columns; weight slice (32x1024
// fp16 = 66KB) + whole h smem image (64x2048B = 128KB, XOR-swizzled,
// UNPADDED -> raw 1D bulk-copyable) + 4 mbarriers.
// h is stored PRE-SWIZZLED in global by the producers, so each step is:
// flat barrier -> 4x cp.async.bulk (32KB chunks of 16 batch-rows, one
// mbarrier each; warp wr waits only chunk wr) -> 64 ldmatrix+2xMMA.
// LSU issue cost for h drops from 4096 LDGSTS to 4 bulk instructions.
// Swizzle: 16B-unit index within a 2048B row XORed with (row & 7).
// ---------------------------------------------------------------------------
#define PW 2064                       // weight smem row pitch (2048 + 16 pad)
#define W_BYTES (32*PW)               // 66048
#define SH_OFF  W_BYTES               // h image offset (multiple of 128)
#define SH_BYTES (64*2048)            // 131072
#define MB_OFF  (SH_OFF + SH_BYTES)   // 197120
#define SM_PERSIST (MB_OFF + 64)      // 197184

__global__ __launch_bounds__(256, 1)
void lstm_persist(const __half* __restrict__ Wg,
                  const float* __restrict__ XG, const float* __restrict__ bias,
                  const __half* __restrict__ hz,
                  __half* __restrict__ Hsw,         // [SEQ][64][1024] swizzled
                  __half* __restrict__ Hplain,      // plain copy or nullptr
                  float* __restrict__ hf,
                  unsigned* __restrict__ pflags)    // [128] x8-padded
{
    extern __shared__ __align__(16) char sm[];
    char* sW = sm;
    const uint32_t sbase = smem_u32(sm);
    const uint32_t aAbs = sbase + SH_OFF;
    const uint32_t mb   = sbase + MB_OFF;

    const int tid = threadIdx.x, lane = tid & 31, w = tid >> 5;
    const int wr = w & 3, wc = w >> 2;
    const int g = lane >> 2, tig = lane & 3;
    const int sub = lane >> 3, lr = lane & 7;
    const int n0 = blockIdx.x * 32;

    // ---- init mbarriers (count=1; tx-based completion) ----
    if (tid == 0) {
#pragma unroll
        for (int c = 0; c < 4; c++) mbar_init(mb + c*8, 1);
    }

    // ---- load this block's weight slice into smem (once) ----
    for (int idx = tid; idx < 4096; idx += 256) {
        int r = idx >> 7, s = idx & 127;
        *(uint4*)(sW + r*PW + s*16) =
            *(const uint4*)(Wg + ((size_t)(n0 + r) << 10) + s*8);
    }
    __syncthreads();

    // ldmatrix addressing: row r, unit(ks,sd) = (ks*2+sd) ^ (r&7)
    const int rA = 16*wr + (sub & 1)*8 + lr;       // this lane's A row
    const int rx = rA & 7;
    const uint32_t abase = aAbs + rA*2048;
    const int sd = sub >> 1;                       // 0/1

    const int brow0 = (wc*16 + g)*PW;
    const int brow1 = (wc*16 + 8 + g)*PW;
    const int m1 = 16*wr + g, m2 = m1 + 8;
    const int Jc0 = n0 + wc*16 + tig*2;
    const int Jc1 = Jc0 + 8;
    const float2 bb0 = *(const float2*)&bias[Jc0];
    const float2 bb1 = *(const float2*)&bias[Jc1];
    const bool co = (tig & 1);
    const int u0 = Jc0 >> 2, u1 = Jc1 >> 2;

    float cc00 = 0.f, cc01 = 0.f, cc10 = 0.f, cc11 = 0.f;

    for (int t = 0; t < SEQ; t++) {
        const __half* ph = t ? (Hsw + (size_t)(t-1) * BATCH * HID) : hz;
        __half* dsw = Hsw + (size_t)t * BATCH * HID;
        __half* dpl = Hplain ? (Hplain + (size_t)t * BATCH * HID) : nullptr;

        // prefetch xg for this step (independent of the recurrence chain)
        const float* xb = XG + (((size_t)(t*64)) << 12);
        const float2 x1_0 = *(const float2*)(xb + (size_t)m1*G4 + Jc0);
        const float2 x2_0 = *(const float2*)(xb + (size_t)m2*G4 + Jc0);
        const float2 x1_1 = *(const float2*)(xb + (size_t)m1*G4 + Jc1);
        const float2 x2_1 = *(const float2*)(xb + (size_t)m2*G4 + Jc1);

        // ---- issue 4 bulk copies (16 batch-rows = 32KB each) ----
        if (tid == 0) {
            fence_proxy_async_cta();
#pragma unroll
            for (int c = 0; c < 4; c++) {
                mbar_expect_tx(mb + c*8, 32768);
                cpa_bulk(aAbs + c*32768, ph + (size_t)c*16*HID, 32768, mb + c*8);
            }
        }

        // ---- wait for this warp's chunk, then full-k MMA sweep ----
        mbar_wait(mb + wr*8, (unsigned)(t & 1));

        float acc0[4] = {0.f, 0.f, 0.f, 0.f};
        float acc1[4] = {0.f, 0.f, 0.f, 0.f};
#pragma unroll 8
        for (int ks = 0; ks < 64; ks++) {
            uint32_t a0[4];
            uint32_t aaddr = abase + ((uint32_t)((ks*2 + sd) ^ rx) << 4);
            ldmatrix_x4(a0, aaddr);
            const int ko = ks*32 + tig*4;
            uint32_t b0[2], b1[2];
            b0[0] = *(const uint32_t*)(sW + brow0 + ko);
            b0[1] = *(const uint32_t*)(sW + brow0 + ko + 16);
            b1[0] = *(const uint32_t*)(sW + brow1 + ko);
            b1[1] = *(const uint32_t*)(sW + brow1 + ko + 16);
            mma16816(acc0, a0, b0);
            mma16816(acc1, a0, b1);
        }

        // ---- pointwise epilogue (hardware-approx activations) ----
        // swizzled store: byte = m*2048 + (((u>>3) ^ (m&7))<<4) + (u&7)*2
        {
            float p0 = acc0[0] + x1_0.x + bb0.x;
            float p1 = acc0[1] + x1_0.y + bb0.y;
            float p2 = acc0[2] + x2_0.x + bb0.x;
            float p3 = acc0[3] + x2_0.y + bb0.y;
            float a0v = co ? fast_tanh(p0) : fast_sig(p0);
            float a1v = fast_sig(p1);
            float a2v = co ? fast_tanh(p2) : fast_sig(p2);
            float a3v = fast_sig(p3);
            float C1 = __shfl_xor_sync(0xFFFFFFFFu, a0v, 1);
            float O1 = __shfl_xor_sync(0xFFFFFFFFu, a1v, 1);
            float C2 = __shfl_xor_sync(0xFFFFFFFFu, a2v, 1);
            float O2 = __shfl_xor_sync(0xFFFFFFFFu, a3v, 1);
            if (!co) {
                cc00 = a0v * cc00 + a1v * C1;
                float hv = O1 * fast_tanh(cc00);
                __half hh = __float2half(hv);
                *(__half*)((char*)dsw + m1*2048 +
                           ((((u0 >> 3) ^ (m1 & 7)) << 4) | ((u0 & 7) << 1))) = hh;
                if (dpl) dpl[m1*HID + u0] = hh;
                if (hf && t == SEQ-1) hf[m1*HID + u0] = hv;
                cc01 = a2v * cc01 + a3v * C2;
                hv = O2 * fast_tanh(cc01);
                hh = __float2half(hv);
                *(__half*)((char*)dsw + m2*2048 +
                           ((((u0 >> 3) ^ (m2 & 7)) << 4) | ((u0 & 7) << 1))) = hh;
                if (dpl) dpl[m2*HID + u0] = hh;
                if (hf && t == SEQ-1) hf[m2*HID + u0] = hv;
            }
        }
        {
            float p0 = acc1[0] + x1_1.x + bb1.x;
            float p1 = acc1[1] + x1_1.y + bb1.y;
            float p2 = acc1[2] + x2_1.x + bb1.x;
            float p3 = acc1[3] + x2_1.y + bb1.y;
            float a0v = co ? fast_tanh(p0) : fast_sig(p0);
            float a1v = fast_sig(p1);
            float a2v = co ? fast_tanh(p2) : fast_sig(p2);
            float a3v = fast_sig(p3);
            float C1 = __shfl_xor_sync(0xFFFFFFFFu, a0v, 1);
            float O1 = __shfl_xor_sync(0xFFFFFFFFu, a1v, 1);
            float C2 = __shfl_xor_sync(0xFFFFFFFFu, a2v, 1);
            float O2 = __shfl_xor_sync(0xFFFFFFFFu, a3v, 1);
            if (!co) {
                cc10 = a0v * cc10 + a1v * C1;
                float hv = O1 * fast_tanh(cc10);
                __half hh = __float2half(hv);
                *(__half*)((char*)dsw + m1*2048 +
                           ((((u1 >> 3) ^ (m1 & 7)) << 4) | ((u1 & 7) << 1))) = hh;
                if (dpl) dpl[m1*HID + u1] = hh;
                if (hf && t == SEQ-1) hf[m1*HID + u1] = hv;
                cc11 = a2v * cc11 + a3v * C2;
                hv = O2 * fast_tanh(cc11);
                hh = __float2half(hv);
                *(__half*)((char*)dsw + m2*2048 +
                           ((((u1 >> 3) ^ (m2 & 7)) << 4) | ((u1 & 7) << 1))) = hh;
                if (dpl) dpl[m2*HID + u1] = hh;
                if (hf && t == SEQ-1) hf[m2*HID + u1] = hv;
            }
        }

        // ---- flat one-hop grid barrier (skip after last step) ----
        if (t != SEQ-1) {
            const unsigned sense = (unsigned)(t + 1);
            __syncthreads();              // all h stores + smem reads done
            if (tid == 0)
                st_release(pflags + blockIdx.x*8, sense);
            if (tid < 128) {
                const unsigned* f = pflags + tid*8;
                while (ld_acquire(f) < sense) {}
            }
            __syncthreads();
        }
    }
}

// ---------------------------------------------------------------------------
// Output projection: out[64][N] = A[64][K] @ B[K][N] + bias (fp32)
// ---------------------------------------------------------------------------
__global__ __launch_bounds__(256)
void sgemm_out(const float* __restrict__ A, const float* __restrict__ B,
               float* __restrict__ Cmat, int N, int K, const float* __restrict__ bias)
{
    __shared__ __align__(16) float As[16][68];
    __shared__ __align__(16) float Bs[16][68];

    const int tid = threadIdx.x;
    const int tx = tid & 15, ty = tid >> 4;
    const int n0 = blockIdx.x * 64;

    float acc[4][4];
#pragma unroll
    for (int r = 0; r < 4; r++)
#pragma unroll
        for (int c = 0; c < 4; c++) acc[r][c] = 0.f;

    const int am = tid >> 2;
    const int akg = tid & 3;
    const int bk = tid >> 4;
    const int bn4 = tid & 15;

    for (int k0 = 0; k0 < K; k0 += 16) {
        float4 av = *(const float4*)&A[(size_t)am * K + k0 + akg * 4];
        float4 bv;
        if (n0 + bn4 * 4 < N)
            bv = *(const float4*)&B[(size_t)(k0 + bk) * N + n0 + bn4 * 4];
        else
            bv = make_float4(0.f, 0.f, 0.f, 0.f);
        As[akg*4 + 0][am] = av.x;
        As[akg*4 + 1][am] = av.y;
        As[akg*4 + 2][am] = av.z;
        As[akg*4 + 3][am] = av.w;
        *(float4*)&Bs[bk][bn4 * 4] = bv;
        __syncthreads();
#pragma unroll
        for (int kk = 0; kk < 16; kk++) {
            float4 a4 = *(const float4*)&As[kk][ty * 4];
            float4 b4 = *(const float4*)&Bs[kk][tx * 4];
            acc[0][0] = fmaf(a4.x, b4.x, acc[0][0]);
            acc[0][1] = fmaf(a4.x, b4.y, acc[0][1]);
            acc[0][2] = fmaf(a4.x, b4.z, acc[0][2]);
            acc[0][3] = fmaf(a4.x, b4.w, acc[0][3]);
            acc[1][0] = fmaf(a4.y, b4.x, acc[1][0]);
            acc[1][1] = fmaf(a4.y, b4.y, acc[1][1]);
            acc[1][2] = fmaf(a4.y, b4.z, acc[1][2]);
            acc[1][3] = fmaf(a4.y, b4.w, acc[1][3]);
            acc[2][0] = fmaf(a4.z, b4.x, acc[2][0]);
            acc[2][1] = fmaf(a4.z, b4.y, acc[2][1]);
            acc[2][2] = fmaf(a4.z, b4.z, acc[2][2]);
            acc[2][3] = fmaf(a4.z, b4.w, acc[2][3]);
            acc[3][0] = fmaf(a4.w, b4.x, acc[3][0]);
            acc[3][1] = fmaf(a4.w, b4.y, acc[3][1]);
            acc[3][2] = fmaf(a4.w, b4.z, acc[3][2]);
            acc[3][3] = fmaf(a4.w, b4.w, acc[3][3]);
        }
        __syncthreads();
    }

#pragma unroll
    for (int r = 0; r < 4; r++) {
        int m = ty * 4 + r;
#pragma unroll
        for (int c = 0; c < 4; c++) {
            int n = n0 + tx * 4 + c;
            if (n < N) Cmat[(size_t)m * N + n] = acc[r][c] + bias[n];
        }
    }
}

// ---------------------------------------------------------------------------
// Host launcher (graph-capturable: kernel launches only)
// ---------------------------------------------------------------------------
extern "C" void kernel_launch(void* const* d_in, const int* in_sizes, int n_in,
                              void* d_out, int out_size)
{
    const int*   X     = (const int*)  d_in[0];
    const float* Cemb  = (const float*)d_in[1];
    const float* W_fx  = (const float*)d_in[2];
    const float* W_fh  = (const float*)d_in[3];
    const float* W_ix  = (const float*)d_in[4];
    const float* W_ih  = (const float*)d_in[5];
    const float* W_Cx  = (const float*)d_in[6];
    const float* W_Ch  = (const float*)d_in[7];
    const float* W_ox  = (const float*)d_in[8];
    const float* W_oh  = (const float*)d_in[9];
    const float* W_fx1 = (const float*)d_in[10];
    const float* W_fh1 = (const float*)d_in[11];
    const float* W_ix1 = (const float*)d_in[12];
    const float* W_ih1 = (const float*)d_in[13];   // unused (reference bug kept)
    const float* W_Cx1 = (const float*)d_in[14];
    const float* W_Ch1 = (const float*)d_in[15];
    const float* W_ox1 = (const float*)d_in[16];
    const float* W_oh1 = (const float*)d_in[17];
    const float* W_out = (const float*)d_in[18];
    const float* b_f   = (const float*)d_in[19];
    const float* b_i   = (const float*)d_in[20];
    const float* b_C   = (const float*)d_in[21];
    const float* b_o   = (const float*)d_in[22];
    const float* b_f1  = (const float*)d_in[23];
    const float* b_i1  = (const float*)d_in[24];
    const float* b_C1  = (const float*)d_in[25];
    const float* b_o1  = (const float*)d_in[26];
    const float* b_out = (const float*)d_in[27];
    float* out = (float*)d_out;
    (void)W_ih1; (void)n_in; (void)in_sizes; (void)out_size;

    __half *E, *H, *Hsw, *H1sw, *B0, *B1, *R0, *R1, *hz;
    float *XG0, *XG1, *b0, *b1, *h1f;
    unsigned *pflags;
    cudaGetSymbolAddress((void**)&E,    g_E);
    cudaGetSymbolAddress((void**)&H,    g_H);
    cudaGetSymbolAddress((void**)&Hsw,  g_Hsw);
    cudaGetSymbolAddress((void**)&H1sw, g_H1sw);
    cudaGetSymbolAddress((void**)&B0, g_B0);
    cudaGetSymbolAddress((void**)&B1, g_B1);
    cudaGetSymbolAddress((void**)&R0, g_R0);
    cudaGetSymbolAddress((void**)&R1, g_R1);
    cudaGetSymbolAddress((void**)&XG0, g_XG0);
    cudaGetSymbolAddress((void**)&XG1, g_XG1);
    cudaGetSymbolAddress((void**)&b0, g_b0);
    cudaGetSymbolAddress((void**)&b1, g_b1);
    cudaGetSymbolAddress((void**)&hz,  g_hz);
    cudaGetSymbolAddress((void**)&h1f, g_h1f);
    cudaGetSymbolAddress((void**)&pflags, g_pflags);

    cudaFuncSetAttribute(lstm_persist,
                         cudaFuncAttributeMaxDynamicSharedMemorySize, SM_PERSIST);
    cudaFuncSetAttribute(mm_mma,
                         cudaFuncAttributeMaxDynamicSharedMemorySize, MM_SMEM);

    // All 16 weight conversions in one launch
    WcvtArgs wa;
    const float* srcs[16] = {W_fx, W_ix, W_Cx, W_ox,
                             W_fx1, W_ix1, W_Cx1, W_ox1,
                             W_fh,  W_ih,  W_Ch,  W_oh,
                             W_fh1, W_ih,  W_Ch1, W_oh1};  // layer1 i-gate = W_ih (ref bug)
    for (int z = 0; z < 16; z++) {
        wa.src[z] = srcs[z];
        wa.g[z] = z & 3;
        if (z < 4)       { wa.dst[z] = B0; wa.K[z] = EMB; }
        else if (z < 8)  { wa.dst[z] = B1; wa.K[z] = HID; }
        else if (z < 12) { wa.dst[z] = R0; wa.K[z] = HID; }
        else             { wa.dst[z] = R1; wa.K[z] = HID; }
    }
    wcvt_all<<<dim3(32, 32, 16), dim3(32, 8)>>>(wa);

    pack_b4<<<(HID + 255)/256, 256>>>(b_f,  b_i,  b_C,  b_o,  (float4*)b0);
    pack_b4<<<(HID + 255)/256, 256>>>(b_f1, b_i1, b_C1, b_o1, (float4*)b1);

    zero_init<<<(BATCH*HID + 255)/256, 256>>>(hz, pflags);
    embed_f16<<<(ROWS*EMB + 255)/256, 256>>>(X, Cemb, E);

    // XG0 = E @ Wx0 (fp16 HMMA, 3-stage pipeline)
    mm_mma<<<dim3(G4/64, ROWS/128), 256, MM_SMEM>>>(E, B0, XG0, EMB);

    // Layer 0 recurrence: persistent, bulk-copy h streaming
    lstm_persist<<<128, 256, SM_PERSIST>>>(R0, XG0, b0, hz, Hsw, H, nullptr,
                                           pflags);

    // XG1 = H @ Wx1 (fp16 HMMA, 3-stage pipeline; plain-layout H)
    mm_mma<<<dim3(G4/64, ROWS/128), 256, MM_SMEM>>>(H, B1, XG1, HID);

    // Layer 1 recurrence
    lstm_persist<<<128, 256, SM_PERSIST>>>(R1, XG1, b1, hz, H1sw, nullptr, h1f,
                                           pflags + 128*8);

    // out = h1 @ W_out + b_out
    sgemm_out<<<dim3((N_CLASS + 63)/64, 1), 256>>>(h1f, W_out, out,
                                                   N_CLASS, HID, b_out);
}